// round 12
// baseline (speedup 1.0000x reference)
#include <cuda_runtime.h>
#include <cuda_fp16.h>
#include <cstdint>
#include <math.h>

#define NROWS 8192
#define CDIM  512
#define DK    64
#define NT_TILES (NROWS / 64)

// Scratch (static __device__ globals — allocation-free per harness rules)
// Q/K pre-split into fp16 hi/lo, pair-interleaved: half2 [row][k2] (k2 = k/2)
__device__ __half2 g_Q1h[NROWS * 32];
__device__ __half2 g_Q1l[NROWS * 32];
__device__ __half2 g_K1h[NROWS * 32];
__device__ __half2 g_K1l[NROWS * 32];
__device__ __half2 g_Q2h[NROWS * 32];
__device__ __half2 g_Q2l[NROWS * 32];
__device__ __half2 g_K2h[NROWS * 32];
__device__ __half2 g_K2l[NROWS * 32];
// V fp16, pair-interleaved: half2 at [k>>1][n] holds (V[k][n], V[k+1][n])
__device__ __half g_V1[NROWS * CDIM];
__device__ __half g_V2[NROWS * CDIM];

// ---------------------------------------------------------------------------
// helpers
// ---------------------------------------------------------------------------
__device__ __forceinline__ void mma16(float c[4], const unsigned a[4],
                                      unsigned b0, unsigned b1) {
    asm volatile(
        "mma.sync.aligned.m16n8k16.row.col.f32.f16.f16.f32 "
        "{%0,%1,%2,%3},{%4,%5,%6,%7},{%8,%9},{%0,%1,%2,%3};"
        : "+f"(c[0]), "+f"(c[1]), "+f"(c[2]), "+f"(c[3])
        : "r"(a[0]), "r"(a[1]), "r"(a[2]), "r"(a[3]), "r"(b0), "r"(b1));
}

__device__ __forceinline__ void splith(float v, __half& h, __half& l) {
    h = __float2half_rn(v);
    l = __float2half_rn(v - __half2float(h));
}

__device__ __forceinline__ unsigned h2u(__half2 h) {
    return *reinterpret_cast<unsigned*>(&h);
}

__device__ __forceinline__ unsigned smem_u32(const void* p) {
    unsigned a;
    asm("{ .reg .u64 t; cvta.to.shared.u64 t, %1; cvt.u32.u64 %0, t; }"
        : "=r"(a) : "l"(p));
    return a;
}

__device__ __forceinline__ void cp16(unsigned dst, const void* src) {
    asm volatile("cp.async.cg.shared.global [%0], [%1], 16;"
                 :: "r"(dst), "l"(src) : "memory");
}
#define CP_COMMIT() asm volatile("cp.async.commit_group;" ::: "memory")
#define CP_WAIT0()  asm volatile("cp.async.wait_group 0;" ::: "memory")

// ---------------------------------------------------------------------------
// Q/K projections (FFMA fp32), outputs pre-split fp16 hi/lo pair-interleaved.
// 4 products (im1/im2 x Wq/Wk) in one launch via blockIdx.y.
// ---------------------------------------------------------------------------
__global__ __launch_bounds__(256)
void qkproj_kernel(const float* __restrict__ im1, const float* __restrict__ im2,
                   const float* __restrict__ Wq, const float* __restrict__ Wk) {
    const int sel = blockIdx.y;
    const float* X = (sel & 2) ? im2 : im1;
    const float* W = (sel & 1) ? Wk : Wq;
    __half2 *OH, *OL;
    switch (sel) {
        case 0:  OH = g_Q1h; OL = g_Q1l; break;
        case 1:  OH = g_K1h; OL = g_K1l; break;
        case 2:  OH = g_Q2h; OL = g_Q2l; break;
        default: OH = g_K2h; OL = g_K2l; break;
    }
    __shared__ float Xs[64][17];
    __shared__ float Ws[16][64];
    int tid  = threadIdx.x;
    int row0 = blockIdx.x * 64;

    int lr = tid >> 2, lc = (tid & 3) * 4;
    int wr = tid >> 4, wc = (tid & 15) * 4;
    int ty = tid >> 4, tx = tid & 15;

    float acc[4][4];
    #pragma unroll
    for (int i = 0; i < 4; i++)
        #pragma unroll
        for (int j = 0; j < 4; j++) acc[i][j] = 0.f;

    for (int k0 = 0; k0 < CDIM; k0 += 16) {
        __syncthreads();
        float4 xv = *(const float4*)(X + (size_t)(row0 + lr) * CDIM + k0 + lc);
        Xs[lr][lc + 0] = xv.x; Xs[lr][lc + 1] = xv.y;
        Xs[lr][lc + 2] = xv.z; Xs[lr][lc + 3] = xv.w;
        *(float4*)(&Ws[wr][wc]) = *(const float4*)(W + (size_t)(k0 + wr) * DK + wc);
        __syncthreads();
        #pragma unroll
        for (int kk = 0; kk < 16; kk++) {
            float a[4], b[4];
            #pragma unroll
            for (int i = 0; i < 4; i++) a[i] = Xs[ty * 4 + i][kk];
            #pragma unroll
            for (int j = 0; j < 4; j++) b[j] = Ws[kk][tx * 4 + j];
            #pragma unroll
            for (int i = 0; i < 4; i++)
                #pragma unroll
                for (int j = 0; j < 4; j++)
                    acc[i][j] = fmaf(a[i], b[j], acc[i][j]);
        }
    }
    #pragma unroll
    for (int i = 0; i < 4; i++) {
        size_t base = (size_t)(row0 + ty * 4 + i) * 32 + tx * 2;
        __half h0, l0, h1, l1, h2, l2, h3, l3;
        splith(acc[i][0], h0, l0); splith(acc[i][1], h1, l1);
        splith(acc[i][2], h2, l2); splith(acc[i][3], h3, l3);
        uint2 uh, ul;
        uh.x = h2u(__halves2half2(h0, h1)); uh.y = h2u(__halves2half2(h2, h3));
        ul.x = h2u(__halves2half2(l0, l1)); ul.y = h2u(__halves2half2(l2, l3));
        *(uint2*)(OH + base) = uh;
        *(uint2*)(OL + base) = ul;
    }
}

// ---------------------------------------------------------------------------
// V projection with fp16 m16n8k16. Output fp16, pair-interleaved (k,k+1) half2.
// ---------------------------------------------------------------------------
__global__ __launch_bounds__(256)
void vproj_kernel(const float* __restrict__ im1, const float* __restrict__ im2,
                  const float* __restrict__ Wv) {
    const float* X = blockIdx.z ? im2 : im1;
    __half* OUT    = blockIdx.z ? g_V2 : g_V1;
    const int row0 = blockIdx.x * 64;
    const int c0   = blockIdx.y * 64;

    __shared__ __half2 Xs2[64 * 12];
    __shared__ __half2 Ws2[8 * 72];
    const unsigned* Xs2u = (const unsigned*)Xs2;
    const unsigned* Ws2u = (const unsigned*)Ws2;

    int tid = threadIdx.x, w = tid >> 5, lane = tid & 31;
    int lr = lane >> 2, lc = lane & 3;
    int wy = w & 3, wx = w >> 2;

    float acc[4][4];
    #pragma unroll
    for (int j = 0; j < 4; j++)
        #pragma unroll
        for (int c = 0; c < 4; c++) acc[j][c] = 0.f;

    for (int k0 = 0; k0 < CDIM; k0 += 16) {
        __syncthreads();
        {
            int r = tid >> 2, c = (tid & 3) * 4;
            float4 v = *(const float4*)(X + (size_t)(row0 + r) * CDIM + k0 + c);
            Xs2[r * 12 + (tid & 3) * 2 + 0] =
                __halves2half2(__float2half_rn(v.x), __float2half_rn(v.y));
            Xs2[r * 12 + (tid & 3) * 2 + 1] =
                __halves2half2(__float2half_rn(v.z), __float2half_rn(v.w));
            int k2 = tid >> 5, n = (tid & 31) * 2;
            float2 wa = *(const float2*)(Wv + (size_t)(k0 + 2 * k2) * CDIM + c0 + n);
            float2 wb = *(const float2*)(Wv + (size_t)(k0 + 2 * k2 + 1) * CDIM + c0 + n);
            Ws2[k2 * 72 + n + 0] =
                __halves2half2(__float2half_rn(wa.x), __float2half_rn(wb.x));
            Ws2[k2 * 72 + n + 1] =
                __halves2half2(__float2half_rn(wa.y), __float2half_rn(wb.y));
        }
        __syncthreads();
        {
            int r = wy * 16 + lr;
            unsigned a[4];
            a[0] = Xs2u[r * 12 + lc];
            a[1] = Xs2u[(r + 8) * 12 + lc];
            a[2] = Xs2u[r * 12 + 4 + lc];
            a[3] = Xs2u[(r + 8) * 12 + 4 + lc];
            #pragma unroll
            for (int j = 0; j < 4; j++) {
                int n = wx * 32 + j * 8 + lr;
                unsigned b0 = Ws2u[lc * 72 + n];
                unsigned b1 = Ws2u[(lc + 4) * 72 + n];
                mma16(acc[j], a, b0, b1);
            }
        }
    }

    __half2* OUT2 = (__half2*)OUT;
    #pragma unroll
    for (int j = 0; j < 4; j++) {
        int n = c0 + wx * 32 + j * 8 + lc * 2;
        float p0 = __shfl_xor_sync(0xffffffffu, acc[j][0], 4);
        float p1 = __shfl_xor_sync(0xffffffffu, acc[j][1], 4);
        float p2 = __shfl_xor_sync(0xffffffffu, acc[j][2], 4);
        float p3 = __shfl_xor_sync(0xffffffffu, acc[j][3], 4);
        int base = row0 + wy * 16 + lr;
        if (!(lr & 1)) {
            int k2 = base >> 1;
            __half2 h0 = __halves2half2(__float2half_rn(acc[j][0]), __float2half_rn(p0));
            __half2 h1 = __halves2half2(__float2half_rn(acc[j][1]), __float2half_rn(p1));
            uint2 u; u.x = h2u(h0); u.y = h2u(h1);
            *(uint2*)(OUT2 + (size_t)k2 * CDIM + n) = u;
        } else {
            int k2 = (base + 7) >> 1;
            __half2 h0 = __halves2half2(__float2half_rn(p2), __float2half_rn(acc[j][2]));
            __half2 h1 = __halves2half2(__float2half_rn(p3), __float2half_rn(acc[j][3]));
            uint2 u; u.x = h2u(h0); u.y = h2u(h1);
            *(uint2*)(OUT2 + (size_t)k2 * CDIM + n) = u;
        }
    }
}

// ---------------------------------------------------------------------------
// Fused flash attention, fp16 m16n8k16, cp.async double-buffered staging,
// warp-local softmax, conditional rescale.
// CTA: 128 q-rows x 256 cols, key tiles of 64, 256 threads (8 warps).
// ---------------------------------------------------------------------------
#define QS2   40                 // half2 stride for Q/K/P smem tiles
#define VS2   272                // half2 stride for V smem tile
#define QH_OFF 0                 // 128*40*4 = 20480
#define QL_OFF 20480
#define K_OFF  40960             // per stage 20480 (hi 10240 + lo 10240), x2
#define V_OFF  81920             // per stage 34816, x2
#define P_OFF  151552            // 128*40*4 = 20480
#define DYN_SZ 172032

__global__ __launch_bounds__(256, 1)
void attn_mma_kernel(const float* __restrict__ im1, const float* __restrict__ im2,
                     float* __restrict__ out) {
    const __half2 *Qh_g, *Ql_g, *Kh_g, *Kl_g;
    const __half* Vh;
    const float* R;
    float* O;
    if (blockIdx.z == 0) {
        Qh_g = g_Q2h; Ql_g = g_Q2l; Kh_g = g_K1h; Kl_g = g_K1l;
        Vh = g_V1; R = im1; O = out;
    } else {
        Qh_g = g_Q1h; Ql_g = g_Q1l; Kh_g = g_K2h; Kl_g = g_K2l;
        Vh = g_V2; R = im2; O = out + (size_t)NROWS * CDIM;
    }
    const int q0   = blockIdx.x * 128;
    const int col0 = blockIdx.y * 256;

    extern __shared__ char dyn[];
    __shared__ float s_dden[128];
    __shared__ float s_fb[128];
    __shared__ int   s_flag[2];

    const unsigned dynb = smem_u32(dyn);
    const __half2* Vg2  = (const __half2*)Vh;

    const int tid  = threadIdx.x;
    const int w    = tid >> 5, lane = tid & 31;
    const int lr   = lane >> 2, lc = lane & 3;
    const int wm   = w & 3, wn = w >> 2;
    const int rb   = w * 16;            // logit row base for this warp

    unsigned* Qh2u = (unsigned*)(dyn + QH_OFF);
    unsigned* Ql2u = (unsigned*)(dyn + QL_OFF);
    unsigned* Ps2u = (unsigned*)(dyn + P_OFF);
    __half2*  Ps2  = (__half2*)(dyn + P_OFF);

    // ---- load Q tile once (pre-split hi/lo) into stride-40 smem ----
    #pragma unroll
    for (int t = 0; t < 4; t++) {
        int e = tid + t * 256;
        int r = e >> 3, c = (e & 7) * 4;          // 8 uint4 per row
        uint4 vh4 = *(const uint4*)(Qh_g + (size_t)(q0 + r) * 32 + c);
        uint4 vl4 = *(const uint4*)(Ql_g + (size_t)(q0 + r) * 32 + c);
        *(uint4*)(Qh2u + r * QS2 + c) = vh4;
        *(uint4*)(Ql2u + r * QS2 + c) = vl4;
    }
    if (tid < 2) s_flag[tid] = 0;

    float acc[2][16][4];
    #pragma unroll
    for (int i = 0; i < 2; i++)
        #pragma unroll
        for (int j = 0; j < 16; j++)
            #pragma unroll
            for (int c = 0; c < 4; c++) acc[i][j][c] = 0.f;

    float mold0 = -INFINITY, mold1 = -INFINITY;
    float dd0 = 0.f, dd1 = 0.f;

    // ---- stage tile 0 ----
    // K hi/lo tile: 64 rows x 8 uint4 x 2 = 1024 cp16 -> 4 iters of 256.
    {
        #pragma unroll
        for (int it = 0; it < 4; it++) {
            int e = tid + it * 256;
            int half = e >> 9, r = (e >> 3) & 63, c = e & 7;
            const __half2* src = (half ? Kl_g : Kh_g) + (size_t)r * 32 + c * 4;
            cp16(dynb + K_OFF + half * 10240 + r * 160 + c * 16, src);
        }
        #pragma unroll
        for (int it = 0; it < 8; it++) {
            int e = tid + it * 256;
            int r = e >> 6, c = e & 63;
            const __half2* src = Vg2 + (size_t)r * CDIM + col0 + c * 4;
            cp16(dynb + V_OFF + r * 1088 + c * 16, src);
        }
        CP_COMMIT();
    }

    for (int kt = 0; kt < NT_TILES; kt++) {
        const int s = kt & 1;
        CP_WAIT0();
        __syncthreads();                                   // sync1

        // ---- issue cp.async for tile kt+1 into the other buffer ----
        if (kt + 1 < NT_TILES) {
            const int k0n = (kt + 1) * 64, sn = s ^ 1;
            #pragma unroll
            for (int it = 0; it < 4; it++) {
                int e = tid + it * 256;
                int half = e >> 9, r = (e >> 3) & 63, c = e & 7;
                const __half2* src = (half ? Kl_g : Kh_g) + (size_t)(k0n + r) * 32 + c * 4;
                cp16(dynb + K_OFF + sn * 20480 + half * 10240 + r * 160 + c * 16, src);
            }
            #pragma unroll
            for (int it = 0; it < 8; it++) {
                int e = tid + it * 256;
                int r = e >> 6, c = e & 63;
                const __half2* src = Vg2 + (size_t)((k0n >> 1) + r) * CDIM + col0 + c * 4;
                cp16(dynb + V_OFF + sn * 34816 + r * 1088 + c * 16, src);
            }
            CP_COMMIT();
        }

        const unsigned* Kh2u = (const unsigned*)(dyn + K_OFF + s * 20480);
        const unsigned* Kl2u = (const unsigned*)(dyn + K_OFF + s * 20480 + 10240);
        const unsigned* Vs2u = (const unsigned*)(dyn + V_OFF + s * 34816);

        // ---- logits: warp-local 16 rows x 64 cols, fp16 3-product split ----
        float L[8][4];
        #pragma unroll
        for (int j = 0; j < 8; j++)
            #pragma unroll
            for (int c = 0; c < 4; c++) L[j][c] = 0.f;

        #pragma unroll
        for (int kk = 0; kk < 4; kk++) {
            const int kc2 = kk * 8;
            unsigned ah[4], al[4];
            int r = rb + lr;
            ah[0] = Qh2u[r * QS2 + kc2 + lc];
            ah[1] = Qh2u[(r + 8) * QS2 + kc2 + lc];
            ah[2] = Qh2u[r * QS2 + kc2 + 4 + lc];
            ah[3] = Qh2u[(r + 8) * QS2 + kc2 + 4 + lc];
            al[0] = Ql2u[r * QS2 + kc2 + lc];
            al[1] = Ql2u[(r + 8) * QS2 + kc2 + lc];
            al[2] = Ql2u[r * QS2 + kc2 + 4 + lc];
            al[3] = Ql2u[(r + 8) * QS2 + kc2 + 4 + lc];
            #pragma unroll
            for (int j = 0; j < 8; j++) {
                int n = j * 8 + lr;
                unsigned bh0 = Kh2u[n * QS2 + kc2 + lc];
                unsigned bh1 = Kh2u[n * QS2 + kc2 + 4 + lc];
                unsigned bl0 = Kl2u[n * QS2 + kc2 + lc];
                unsigned bl1 = Kl2u[n * QS2 + kc2 + 4 + lc];
                mma16(L[j], ah, bh0, bh1);
                mma16(L[j], al, bh0, bh1);
                mma16(L[j], ah, bl0, bl1);
            }
        }

        // ---- warp-local softmax ----
        float m0 = -INFINITY, m1 = -INFINITY;
        #pragma unroll
        for (int j = 0; j < 8; j++) {
            m0 = fmaxf(m0, fmaxf(L[j][0], L[j][1]));
            m1 = fmaxf(m1, fmaxf(L[j][2], L[j][3]));
        }
        m0 = fmaxf(m0, __shfl_xor_sync(0xffffffffu, m0, 1));
        m0 = fmaxf(m0, __shfl_xor_sync(0xffffffffu, m0, 2));
        m1 = fmaxf(m1, __shfl_xor_sync(0xffffffffu, m1, 1));
        m1 = fmaxf(m1, __shfl_xor_sync(0xffffffffu, m1, 2));
        const float mn0 = fmaxf(mold0, m0);
        const float mn1 = fmaxf(mold1, m1);
        const float f0 = __expf(mold0 - mn0);
        const float f1 = __expf(mold1 - mn1);
        const bool changed = (m0 > mold0) || (m1 > mold1);
        mold0 = mn0; mold1 = mn1;

        float rs0 = 0.f, rs1 = 0.f;
        #pragma unroll
        for (int j = 0; j < 8; j++) {
            float p0 = __expf(L[j][0] - mn0);
            float p1 = __expf(L[j][1] - mn0);
            float p2 = __expf(L[j][2] - mn1);
            float p3 = __expf(L[j][3] - mn1);
            rs0 += p0 + p1;
            rs1 += p2 + p3;
            int c2 = 4 * j + lc;
            Ps2[(rb + lr) * QS2 + c2]     = __floats2half2_rn(p0, p1);
            Ps2[(rb + lr + 8) * QS2 + c2] = __floats2half2_rn(p2, p3);
        }
        rs0 += __shfl_xor_sync(0xffffffffu, rs0, 1);
        rs0 += __shfl_xor_sync(0xffffffffu, rs0, 2);
        rs1 += __shfl_xor_sync(0xffffffffu, rs1, 1);
        rs1 += __shfl_xor_sync(0xffffffffu, rs1, 2);
        dd0 = dd0 * f0 + rs0;
        dd1 = dd1 * f1 + rs1;

        if (lc == 0) { s_fb[rb + lr] = f0; s_fb[rb + lr + 8] = f1; }
        if (__any_sync(0xffffffffu, changed) && lane == 0) s_flag[s] = 1;

        __syncthreads();                                   // sync2

        const bool resc = (s_flag[s] != 0);
        if (tid == 0) s_flag[s ^ 1] = 0;

        // ---- conditional rescale of PV accumulators ----
        if (resc) {
            #pragma unroll
            for (int i = 0; i < 2; i++) {
                int r = wm * 32 + i * 16 + lr;
                float g0 = s_fb[r], g1 = s_fb[r + 8];
                #pragma unroll
                for (int j = 0; j < 16; j++) {
                    acc[i][j][0] *= g0; acc[i][j][1] *= g0;
                    acc[i][j][2] *= g1; acc[i][j][3] *= g1;
                }
            }
        }

        // ---- PV: O += P @ V ----
        #pragma unroll
        for (int kk = 0; kk < 4; kk++) {
            const int kc2 = kk * 8;
            unsigned a[2][4];
            #pragma unroll
            for (int i = 0; i < 2; i++) {
                int r = wm * 32 + i * 16 + lr;
                a[i][0] = Ps2u[r * QS2 + kc2 + lc];
                a[i][1] = Ps2u[(r + 8) * QS2 + kc2 + lc];
                a[i][2] = Ps2u[r * QS2 + kc2 + 4 + lc];
                a[i][3] = Ps2u[(r + 8) * QS2 + kc2 + 4 + lc];
            }
            #pragma unroll
            for (int j = 0; j < 16; j++) {
                int n = wn * 128 + j * 8 + lr;
                unsigned b0 = Vs2u[(kc2 + lc) * VS2 + n];
                unsigned b1 = Vs2u[(kc2 + lc + 4) * VS2 + n];
                mma16(acc[0][j], a[0], b0, b1);
                mma16(acc[1][j], a[1], b0, b1);
            }
        }
    }

    // ---- publish denominators, then epilogue ----
    if (lc == 0) { s_dden[rb + lr] = dd0; s_dden[rb + lr + 8] = dd1; }
    __syncthreads();

    #pragma unroll
    for (int i = 0; i < 2; i++) {
        int r = wm * 32 + i * 16 + lr;
        float inv0 = 1.f / s_dden[r];
        float inv1 = 1.f / s_dden[r + 8];
        size_t g0 = (size_t)(q0 + r) * CDIM;
        size_t g1 = (size_t)(q0 + r + 8) * CDIM;
        #pragma unroll
        for (int j = 0; j < 16; j++) {
            int c = col0 + wn * 128 + j * 8 + lc * 2;
            float2 r0 = *(const float2*)(R + g0 + c);
            float2 r1 = *(const float2*)(R + g1 + c);
            float2 o0 = make_float2(fmaf(acc[i][j][0], inv0, r0.x),
                                    fmaf(acc[i][j][1], inv0, r0.y));
            float2 o1 = make_float2(fmaf(acc[i][j][2], inv1, r1.x),
                                    fmaf(acc[i][j][3], inv1, r1.y));
            *(float2*)(O + g0 + c) = o0;
            *(float2*)(O + g1 + c) = o1;
        }
    }
}

// ---------------------------------------------------------------------------
extern "C" void kernel_launch(void* const* d_in, const int* in_sizes, int n_in,
                              void* d_out, int out_size) {
    const float* im1 = (const float*)d_in[0];
    const float* im2 = (const float*)d_in[1];
    const float* Wq  = (const float*)d_in[2];
    const float* Wk  = (const float*)d_in[3];
    const float* Wv  = (const float*)d_in[4];
    float* out = (float*)d_out;

    qkproj_kernel<<<dim3(NROWS / 64, 4), 256>>>(im1, im2, Wq, Wk);
    vproj_kernel<<<dim3(NROWS / 64, CDIM / 64, 2), 256>>>(im1, im2, Wv);

    cudaFuncSetAttribute(attn_mma_kernel,
                         cudaFuncAttributeMaxDynamicSharedMemorySize, DYN_SZ);
    attn_mma_kernel<<<dim3(NROWS / 128, CDIM / 256, 2), 256, DYN_SZ>>>(im1, im2, out);
}

// round 13
// speedup vs baseline: 1.2145x; 1.2145x over previous
#include <cuda_runtime.h>
#include <cuda_fp16.h>
#include <cstdint>
#include <math.h>

#define NROWS 8192
#define CDIM  512
#define DK    64
#define NT_TILES (NROWS / 64)

// Scratch (static __device__ globals — allocation-free per harness rules)
// Q/K pre-split into fp16 hi/lo, pair-interleaved: half2 [row][k2] (k2 = k/2)
__device__ __half2 g_Q1h[NROWS * 32];
__device__ __half2 g_Q1l[NROWS * 32];
__device__ __half2 g_K1h[NROWS * 32];
__device__ __half2 g_K1l[NROWS * 32];
__device__ __half2 g_Q2h[NROWS * 32];
__device__ __half2 g_Q2l[NROWS * 32];
__device__ __half2 g_K2h[NROWS * 32];
__device__ __half2 g_K2l[NROWS * 32];
// V fp16, pair-interleaved: half2 at [k>>1][n] holds (V[k][n], V[k+1][n])
__device__ __half g_V1[NROWS * CDIM];
__device__ __half g_V2[NROWS * CDIM];

// ---------------------------------------------------------------------------
// helpers
// ---------------------------------------------------------------------------
__device__ __forceinline__ void mma16(float c[4], const unsigned a[4],
                                      unsigned b0, unsigned b1) {
    asm volatile(
        "mma.sync.aligned.m16n8k16.row.col.f32.f16.f16.f32 "
        "{%0,%1,%2,%3},{%4,%5,%6,%7},{%8,%9},{%0,%1,%2,%3};"
        : "+f"(c[0]), "+f"(c[1]), "+f"(c[2]), "+f"(c[3])
        : "r"(a[0]), "r"(a[1]), "r"(a[2]), "r"(a[3]), "r"(b0), "r"(b1));
}

__device__ __forceinline__ void splith(float v, __half& h, __half& l) {
    h = __float2half_rn(v);
    l = __float2half_rn(v - __half2float(h));
}

__device__ __forceinline__ unsigned h2u(__half2 h) {
    return *reinterpret_cast<unsigned*>(&h);
}

__device__ __forceinline__ unsigned smem_u32(const void* p) {
    unsigned a;
    asm("{ .reg .u64 t; cvta.to.shared.u64 t, %1; cvt.u32.u64 %0, t; }"
        : "=r"(a) : "l"(p));
    return a;
}

__device__ __forceinline__ void cp16(unsigned dst, const void* src) {
    asm volatile("cp.async.cg.shared.global [%0], [%1], 16;"
                 :: "r"(dst), "l"(src) : "memory");
}
#define CP_COMMIT() asm volatile("cp.async.commit_group;" ::: "memory")
#define CP_WAIT0()  asm volatile("cp.async.wait_group 0;" ::: "memory")

// ---------------------------------------------------------------------------
// Q/K projections (FFMA fp32), outputs pre-split fp16 hi/lo pair-interleaved.
// ---------------------------------------------------------------------------
__global__ __launch_bounds__(256)
void qkproj_kernel(const float* __restrict__ im1, const float* __restrict__ im2,
                   const float* __restrict__ Wq, const float* __restrict__ Wk) {
    const int sel = blockIdx.y;
    const float* X = (sel & 2) ? im2 : im1;
    const float* W = (sel & 1) ? Wk : Wq;
    __half2 *OH, *OL;
    switch (sel) {
        case 0:  OH = g_Q1h; OL = g_Q1l; break;
        case 1:  OH = g_K1h; OL = g_K1l; break;
        case 2:  OH = g_Q2h; OL = g_Q2l; break;
        default: OH = g_K2h; OL = g_K2l; break;
    }
    __shared__ float Xs[64][17];
    __shared__ float Ws[16][64];
    int tid  = threadIdx.x;
    int row0 = blockIdx.x * 64;

    int lr = tid >> 2, lc = (tid & 3) * 4;
    int wr = tid >> 4, wc = (tid & 15) * 4;
    int ty = tid >> 4, tx = tid & 15;

    float acc[4][4];
    #pragma unroll
    for (int i = 0; i < 4; i++)
        #pragma unroll
        for (int j = 0; j < 4; j++) acc[i][j] = 0.f;

    for (int k0 = 0; k0 < CDIM; k0 += 16) {
        __syncthreads();
        float4 xv = *(const float4*)(X + (size_t)(row0 + lr) * CDIM + k0 + lc);
        Xs[lr][lc + 0] = xv.x; Xs[lr][lc + 1] = xv.y;
        Xs[lr][lc + 2] = xv.z; Xs[lr][lc + 3] = xv.w;
        *(float4*)(&Ws[wr][wc]) = *(const float4*)(W + (size_t)(k0 + wr) * DK + wc);
        __syncthreads();
        #pragma unroll
        for (int kk = 0; kk < 16; kk++) {
            float a[4], b[4];
            #pragma unroll
            for (int i = 0; i < 4; i++) a[i] = Xs[ty * 4 + i][kk];
            #pragma unroll
            for (int j = 0; j < 4; j++) b[j] = Ws[kk][tx * 4 + j];
            #pragma unroll
            for (int i = 0; i < 4; i++)
                #pragma unroll
                for (int j = 0; j < 4; j++)
                    acc[i][j] = fmaf(a[i], b[j], acc[i][j]);
        }
    }
    #pragma unroll
    for (int i = 0; i < 4; i++) {
        size_t base = (size_t)(row0 + ty * 4 + i) * 32 + tx * 2;
        __half h0, l0, h1, l1, h2, l2, h3, l3;
        splith(acc[i][0], h0, l0); splith(acc[i][1], h1, l1);
        splith(acc[i][2], h2, l2); splith(acc[i][3], h3, l3);
        uint2 uh, ul;
        uh.x = h2u(__halves2half2(h0, h1)); uh.y = h2u(__halves2half2(h2, h3));
        ul.x = h2u(__halves2half2(l0, l1)); ul.y = h2u(__halves2half2(l2, l3));
        *(uint2*)(OH + base) = uh;
        *(uint2*)(OL + base) = ul;
    }
}

// ---------------------------------------------------------------------------
// V projection with fp16 m16n8k16. Output fp16, pair-interleaved (k,k+1) half2.
// ---------------------------------------------------------------------------
__global__ __launch_bounds__(256)
void vproj_kernel(const float* __restrict__ im1, const float* __restrict__ im2,
                  const float* __restrict__ Wv) {
    const float* X = blockIdx.z ? im2 : im1;
    __half* OUT    = blockIdx.z ? g_V2 : g_V1;
    const int row0 = blockIdx.x * 64;
    const int c0   = blockIdx.y * 64;

    __shared__ __half2 Xs2[64 * 12];
    __shared__ __half2 Ws2[8 * 72];
    const unsigned* Xs2u = (const unsigned*)Xs2;
    const unsigned* Ws2u = (const unsigned*)Ws2;

    int tid = threadIdx.x, w = tid >> 5, lane = tid & 31;
    int lr = lane >> 2, lc = lane & 3;
    int wy = w & 3, wx = w >> 2;

    float acc[4][4];
    #pragma unroll
    for (int j = 0; j < 4; j++)
        #pragma unroll
        for (int c = 0; c < 4; c++) acc[j][c] = 0.f;

    for (int k0 = 0; k0 < CDIM; k0 += 16) {
        __syncthreads();
        {
            int r = tid >> 2, c = (tid & 3) * 4;
            float4 v = *(const float4*)(X + (size_t)(row0 + r) * CDIM + k0 + c);
            Xs2[r * 12 + (tid & 3) * 2 + 0] =
                __halves2half2(__float2half_rn(v.x), __float2half_rn(v.y));
            Xs2[r * 12 + (tid & 3) * 2 + 1] =
                __halves2half2(__float2half_rn(v.z), __float2half_rn(v.w));
            int k2 = tid >> 5, n = (tid & 31) * 2;
            float2 wa = *(const float2*)(Wv + (size_t)(k0 + 2 * k2) * CDIM + c0 + n);
            float2 wb = *(const float2*)(Wv + (size_t)(k0 + 2 * k2 + 1) * CDIM + c0 + n);
            Ws2[k2 * 72 + n + 0] =
                __halves2half2(__float2half_rn(wa.x), __float2half_rn(wb.x));
            Ws2[k2 * 72 + n + 1] =
                __halves2half2(__float2half_rn(wa.y), __float2half_rn(wb.y));
        }
        __syncthreads();
        {
            int r = wy * 16 + lr;
            unsigned a[4];
            a[0] = Xs2u[r * 12 + lc];
            a[1] = Xs2u[(r + 8) * 12 + lc];
            a[2] = Xs2u[r * 12 + 4 + lc];
            a[3] = Xs2u[(r + 8) * 12 + 4 + lc];
            #pragma unroll
            for (int j = 0; j < 4; j++) {
                int n = wx * 32 + j * 8 + lr;
                unsigned b0 = Ws2u[lc * 72 + n];
                unsigned b1 = Ws2u[(lc + 4) * 72 + n];
                mma16(acc[j], a, b0, b1);
            }
        }
    }

    __half2* OUT2 = (__half2*)OUT;
    #pragma unroll
    for (int j = 0; j < 4; j++) {
        int n = c0 + wx * 32 + j * 8 + lc * 2;
        float p0 = __shfl_xor_sync(0xffffffffu, acc[j][0], 4);
        float p1 = __shfl_xor_sync(0xffffffffu, acc[j][1], 4);
        float p2 = __shfl_xor_sync(0xffffffffu, acc[j][2], 4);
        float p3 = __shfl_xor_sync(0xffffffffu, acc[j][3], 4);
        int base = row0 + wy * 16 + lr;
        if (!(lr & 1)) {
            int k2 = base >> 1;
            __half2 h0 = __halves2half2(__float2half_rn(acc[j][0]), __float2half_rn(p0));
            __half2 h1 = __halves2half2(__float2half_rn(acc[j][1]), __float2half_rn(p1));
            uint2 u; u.x = h2u(h0); u.y = h2u(h1);
            *(uint2*)(OUT2 + (size_t)k2 * CDIM + n) = u;
        } else {
            int k2 = (base + 7) >> 1;
            __half2 h0 = __halves2half2(__float2half_rn(p2), __float2half_rn(acc[j][2]));
            __half2 h1 = __halves2half2(__float2half_rn(p3), __float2half_rn(acc[j][3]));
            uint2 u; u.x = h2u(h0); u.y = h2u(h1);
            *(uint2*)(OUT2 + (size_t)k2 * CDIM + n) = u;
        }
    }
}

// ---------------------------------------------------------------------------
// Fused flash attention, fp16 m16n8k16, cp.async double-buffered staging,
// warp-local softmax, conditional rescale.
// Strides reverted to conflict-free values: QS2=36 (banks 4n+lc -> perfect),
// VS2=264 (banks 8lc+n -> perfect).
// ---------------------------------------------------------------------------
#define QS2   36                 // half2 stride for Q/K/P smem tiles (144 B/row)
#define VS2   264                // half2 stride for V smem tile (1056 B/row)
#define QH_OFF 0                 // 128*36*4 = 18432
#define QL_OFF 18432
#define K_OFF  36864             // per stage 18432 (hi 9216 + lo 9216), x2
#define V_OFF  73728             // per stage 33792 (32*264*4), x2
#define P_OFF  141312            // 128*36*4 = 18432
#define DYN_SZ 159744

__global__ __launch_bounds__(256, 1)
void attn_mma_kernel(const float* __restrict__ im1, const float* __restrict__ im2,
                     float* __restrict__ out) {
    const __half2 *Qh_g, *Ql_g, *Kh_g, *Kl_g;
    const __half* Vh;
    const float* R;
    float* O;
    if (blockIdx.z == 0) {
        Qh_g = g_Q2h; Ql_g = g_Q2l; Kh_g = g_K1h; Kl_g = g_K1l;
        Vh = g_V1; R = im1; O = out;
    } else {
        Qh_g = g_Q1h; Ql_g = g_Q1l; Kh_g = g_K2h; Kl_g = g_K2l;
        Vh = g_V2; R = im2; O = out + (size_t)NROWS * CDIM;
    }
    const int q0   = blockIdx.x * 128;
    const int col0 = blockIdx.y * 256;

    extern __shared__ char dyn[];
    __shared__ float s_dden[128];
    __shared__ float s_fb[128];
    __shared__ int   s_flag[2];

    const unsigned dynb = smem_u32(dyn);
    const __half2* Vg2  = (const __half2*)Vh;

    const int tid  = threadIdx.x;
    const int w    = tid >> 5, lane = tid & 31;
    const int lr   = lane >> 2, lc = lane & 3;
    const int wm   = w & 3, wn = w >> 2;
    const int rb   = w * 16;            // logit row base for this warp

    unsigned* Qh2u = (unsigned*)(dyn + QH_OFF);
    unsigned* Ql2u = (unsigned*)(dyn + QL_OFF);
    unsigned* Ps2u = (unsigned*)(dyn + P_OFF);
    __half2*  Ps2  = (__half2*)(dyn + P_OFF);

    // ---- load Q tile once (pre-split hi/lo) into stride-36 smem ----
    #pragma unroll
    for (int t = 0; t < 4; t++) {
        int e = tid + t * 256;
        int r = e >> 3, c = (e & 7) * 4;          // 8 uint4 per row
        uint4 vh4 = *(const uint4*)(Qh_g + (size_t)(q0 + r) * 32 + c);
        uint4 vl4 = *(const uint4*)(Ql_g + (size_t)(q0 + r) * 32 + c);
        *(uint4*)(Qh2u + r * QS2 + c) = vh4;
        *(uint4*)(Ql2u + r * QS2 + c) = vl4;
    }
    if (tid < 2) s_flag[tid] = 0;

    float acc[2][16][4];
    #pragma unroll
    for (int i = 0; i < 2; i++)
        #pragma unroll
        for (int j = 0; j < 16; j++)
            #pragma unroll
            for (int c = 0; c < 4; c++) acc[i][j][c] = 0.f;

    float mold0 = -INFINITY, mold1 = -INFINITY;
    float dd0 = 0.f, dd1 = 0.f;

    // ---- stage tile 0 ----
    // K hi/lo tile: 64 rows x 8 uint4 x 2 = 1024 cp16 -> 4 iters of 256.
    {
        #pragma unroll
        for (int it = 0; it < 4; it++) {
            int e = tid + it * 256;
            int half = e >> 9, r = (e >> 3) & 63, c = e & 7;
            const __half2* src = (half ? Kl_g : Kh_g) + (size_t)r * 32 + c * 4;
            cp16(dynb + K_OFF + half * 9216 + r * 144 + c * 16, src);
        }
        #pragma unroll
        for (int it = 0; it < 8; it++) {
            int e = tid + it * 256;
            int r = e >> 6, c = e & 63;
            const __half2* src = Vg2 + (size_t)r * CDIM + col0 + c * 4;
            cp16(dynb + V_OFF + r * 1056 + c * 16, src);
        }
        CP_COMMIT();
    }

    for (int kt = 0; kt < NT_TILES; kt++) {
        const int s = kt & 1;
        CP_WAIT0();
        __syncthreads();                                   // sync1

        // ---- issue cp.async for tile kt+1 into the other buffer ----
        if (kt + 1 < NT_TILES) {
            const int k0n = (kt + 1) * 64, sn = s ^ 1;
            #pragma unroll
            for (int it = 0; it < 4; it++) {
                int e = tid + it * 256;
                int half = e >> 9, r = (e >> 3) & 63, c = e & 7;
                const __half2* src = (half ? Kl_g : Kh_g) + (size_t)(k0n + r) * 32 + c * 4;
                cp16(dynb + K_OFF + sn * 18432 + half * 9216 + r * 144 + c * 16, src);
            }
            #pragma unroll
            for (int it = 0; it < 8; it++) {
                int e = tid + it * 256;
                int r = e >> 6, c = e & 63;
                const __half2* src = Vg2 + (size_t)((k0n >> 1) + r) * CDIM + col0 + c * 4;
                cp16(dynb + V_OFF + sn * 33792 + r * 1056 + c * 16, src);
            }
            CP_COMMIT();
        }

        const unsigned* Kh2u = (const unsigned*)(dyn + K_OFF + s * 18432);
        const unsigned* Kl2u = (const unsigned*)(dyn + K_OFF + s * 18432 + 9216);
        const unsigned* Vs2u = (const unsigned*)(dyn + V_OFF + s * 33792);

        // ---- logits: warp-local 16 rows x 64 cols, fp16 3-product split ----
        float L[8][4];
        #pragma unroll
        for (int j = 0; j < 8; j++)
            #pragma unroll
            for (int c = 0; c < 4; c++) L[j][c] = 0.f;

        #pragma unroll
        for (int kk = 0; kk < 4; kk++) {
            const int kc2 = kk * 8;
            unsigned ah[4], al[4];
            int r = rb + lr;
            ah[0] = Qh2u[r * QS2 + kc2 + lc];
            ah[1] = Qh2u[(r + 8) * QS2 + kc2 + lc];
            ah[2] = Qh2u[r * QS2 + kc2 + 4 + lc];
            ah[3] = Qh2u[(r + 8) * QS2 + kc2 + 4 + lc];
            al[0] = Ql2u[r * QS2 + kc2 + lc];
            al[1] = Ql2u[(r + 8) * QS2 + kc2 + lc];
            al[2] = Ql2u[r * QS2 + kc2 + 4 + lc];
            al[3] = Ql2u[(r + 8) * QS2 + kc2 + 4 + lc];
            #pragma unroll
            for (int j = 0; j < 8; j++) {
                int n = j * 8 + lr;
                unsigned bh0 = Kh2u[n * QS2 + kc2 + lc];
                unsigned bh1 = Kh2u[n * QS2 + kc2 + 4 + lc];
                unsigned bl0 = Kl2u[n * QS2 + kc2 + lc];
                unsigned bl1 = Kl2u[n * QS2 + kc2 + 4 + lc];
                mma16(L[j], ah, bh0, bh1);
                mma16(L[j], al, bh0, bh1);
                mma16(L[j], ah, bl0, bl1);
            }
        }

        // ---- warp-local softmax ----
        float m0 = -INFINITY, m1 = -INFINITY;
        #pragma unroll
        for (int j = 0; j < 8; j++) {
            m0 = fmaxf(m0, fmaxf(L[j][0], L[j][1]));
            m1 = fmaxf(m1, fmaxf(L[j][2], L[j][3]));
        }
        m0 = fmaxf(m0, __shfl_xor_sync(0xffffffffu, m0, 1));
        m0 = fmaxf(m0, __shfl_xor_sync(0xffffffffu, m0, 2));
        m1 = fmaxf(m1, __shfl_xor_sync(0xffffffffu, m1, 1));
        m1 = fmaxf(m1, __shfl_xor_sync(0xffffffffu, m1, 2));
        const float mn0 = fmaxf(mold0, m0);
        const float mn1 = fmaxf(mold1, m1);
        const float f0 = __expf(mold0 - mn0);
        const float f1 = __expf(mold1 - mn1);
        const bool changed = (m0 > mold0) || (m1 > mold1);
        mold0 = mn0; mold1 = mn1;

        float rs0 = 0.f, rs1 = 0.f;
        #pragma unroll
        for (int j = 0; j < 8; j++) {
            float p0 = __expf(L[j][0] - mn0);
            float p1 = __expf(L[j][1] - mn0);
            float p2 = __expf(L[j][2] - mn1);
            float p3 = __expf(L[j][3] - mn1);
            rs0 += p0 + p1;
            rs1 += p2 + p3;
            int c2 = 4 * j + lc;
            Ps2[(rb + lr) * QS2 + c2]     = __floats2half2_rn(p0, p1);
            Ps2[(rb + lr + 8) * QS2 + c2] = __floats2half2_rn(p2, p3);
        }
        rs0 += __shfl_xor_sync(0xffffffffu, rs0, 1);
        rs0 += __shfl_xor_sync(0xffffffffu, rs0, 2);
        rs1 += __shfl_xor_sync(0xffffffffu, rs1, 1);
        rs1 += __shfl_xor_sync(0xffffffffu, rs1, 2);
        dd0 = dd0 * f0 + rs0;
        dd1 = dd1 * f1 + rs1;

        if (lc == 0) { s_fb[rb + lr] = f0; s_fb[rb + lr + 8] = f1; }
        if (__any_sync(0xffffffffu, changed) && lane == 0) s_flag[s] = 1;

        __syncthreads();                                   // sync2

        const bool resc = (s_flag[s] != 0);
        if (tid == 0) s_flag[s ^ 1] = 0;

        // ---- conditional rescale of PV accumulators ----
        if (resc) {
            #pragma unroll
            for (int i = 0; i < 2; i++) {
                int r = wm * 32 + i * 16 + lr;
                float g0 = s_fb[r], g1 = s_fb[r + 8];
                #pragma unroll
                for (int j = 0; j < 16; j++) {
                    acc[i][j][0] *= g0; acc[i][j][1] *= g0;
                    acc[i][j][2] *= g1; acc[i][j][3] *= g1;
                }
            }
        }

        // ---- PV: O += P @ V ----
        #pragma unroll
        for (int kk = 0; kk < 4; kk++) {
            const int kc2 = kk * 8;
            unsigned a[2][4];
            #pragma unroll
            for (int i = 0; i < 2; i++) {
                int r = wm * 32 + i * 16 + lr;
                a[i][0] = Ps2u[r * QS2 + kc2 + lc];
                a[i][1] = Ps2u[(r + 8) * QS2 + kc2 + lc];
                a[i][2] = Ps2u[r * QS2 + kc2 + 4 + lc];
                a[i][3] = Ps2u[(r + 8) * QS2 + kc2 + 4 + lc];
            }
            #pragma unroll
            for (int j = 0; j < 16; j++) {
                int n = wn * 128 + j * 8 + lr;
                unsigned b0 = Vs2u[(kc2 + lc) * VS2 + n];
                unsigned b1 = Vs2u[(kc2 + lc + 4) * VS2 + n];
                mma16(acc[0][j], a[0], b0, b1);
                mma16(acc[1][j], a[1], b0, b1);
            }
        }
    }

    // ---- publish denominators, then epilogue ----
    if (lc == 0) { s_dden[rb + lr] = dd0; s_dden[rb + lr + 8] = dd1; }
    __syncthreads();

    #pragma unroll
    for (int i = 0; i < 2; i++) {
        int r = wm * 32 + i * 16 + lr;
        float inv0 = 1.f / s_dden[r];
        float inv1 = 1.f / s_dden[r + 8];
        size_t g0 = (size_t)(q0 + r) * CDIM;
        size_t g1 = (size_t)(q0 + r + 8) * CDIM;
        #pragma unroll
        for (int j = 0; j < 16; j++) {
            int c = col0 + wn * 128 + j * 8 + lc * 2;
            float2 r0 = *(const float2*)(R + g0 + c);
            float2 r1 = *(const float2*)(R + g1 + c);
            float2 o0 = make_float2(fmaf(acc[i][j][0], inv0, r0.x),
                                    fmaf(acc[i][j][1], inv0, r0.y));
            float2 o1 = make_float2(fmaf(acc[i][j][2], inv1, r1.x),
                                    fmaf(acc[i][j][3], inv1, r1.y));
            *(float2*)(O + g0 + c) = o0;
            *(float2*)(O + g1 + c) = o1;
        }
    }
}

// ---------------------------------------------------------------------------
extern "C" void kernel_launch(void* const* d_in, const int* in_sizes, int n_in,
                              void* d_out, int out_size) {
    const float* im1 = (const float*)d_in[0];
    const float* im2 = (const float*)d_in[1];
    const float* Wq  = (const float*)d_in[2];
    const float* Wk  = (const float*)d_in[3];
    const float* Wv  = (const float*)d_in[4];
    float* out = (float*)d_out;

    qkproj_kernel<<<dim3(NROWS / 64, 4), 256>>>(im1, im2, Wq, Wk);
    vproj_kernel<<<dim3(NROWS / 64, CDIM / 64, 2), 256>>>(im1, im2, Wv);

    cudaFuncSetAttribute(attn_mma_kernel,
                         cudaFuncAttributeMaxDynamicSharedMemorySize, DYN_SZ);
    attn_mma_kernel<<<dim3(NROWS / 128, CDIM / 256, 2), 256, DYN_SZ>>>(im1, im2, out);
}